// round 2
// baseline (speedup 1.0000x reference)
#include <cuda_runtime.h>
#include <math.h>

#define E 128
#define H 8
#define D 16
#define CTXLEN 257
#define TN 128
#define THREADS 256
#define TANH_CLIP 10.0f

// shared memory layout (floats)
//  s_tile   [TN][132]   16896   (also reused for Wkg/Wko staging at stride 129)
//  s_qk     [8][132]     1056
//  s_compat [8][TN]      1024   (also reused as mean-reduction scratch, 1024 floats)
//  s_p      [8][TN]      1024
//  s_wemb   [8][128]     1024
//  s_vA     [128]         128
//  s_vB     [128]         128
//  s_qk2    [128]         128
//  s_ctx    [260]         260
//  s_logits [1024]       1024
//  s_red    [32]           32
#define SM_TILE   0
#define SM_QK     16896
#define SM_COMPAT (16896+1056)
#define SM_P      (SM_COMPAT+1024)
#define SM_WEMB   (SM_P+1024)
#define SM_VA     (SM_WEMB+1024)
#define SM_VB     (SM_VA+128)
#define SM_QK2    (SM_VB+128)
#define SM_CTX    (SM_QK2+128)
#define SM_LOGITS (SM_CTX+260)
#define SM_RED    (SM_LOGITS+1024)
#define SM_FLOATS (SM_RED+32)

__device__ __forceinline__ float warp_max(float v) {
    #pragma unroll
    for (int o = 16; o; o >>= 1) v = fmaxf(v, __shfl_xor_sync(0xffffffffu, v, o));
    return v;
}
__device__ __forceinline__ float warp_sum(float v) {
    #pragma unroll
    for (int o = 16; o; o >>= 1) v += __shfl_xor_sync(0xffffffffu, v, o);
    return v;
}

__global__ __launch_bounds__(THREADS) void decoder_fused_kernel(
    const float* __restrict__ emb,       // [B,N,E]
    const float* __restrict__ rc,        // [B]
    const float* __restrict__ Wqg,       // [257,E]
    const float* __restrict__ Wkg,       // [E,E]
    const float* __restrict__ Wvg,       // [E,E]
    const float* __restrict__ Wog,       // [E,E]
    const float* __restrict__ Wqo,       // [E,E]
    const float* __restrict__ Wko,       // [E,E]
    const int*   __restrict__ cur,       // [B]
    const unsigned char* __restrict__ mask, // [B,N]
    float* __restrict__ out,             // [2,B,N]: probs then logits
    int N, int B)
{
    extern __shared__ float sm[];
    const int b    = blockIdx.x;
    const int t    = threadIdx.x;
    const int lane = t & 31;
    const int warp = t >> 5;

    const float* embB  = emb  + (size_t)b * N * E;
    const unsigned char* maskB = mask + (size_t)b * N;

    // ---------------- Phase 0: graph mean + context -----------------------
    {
        float4 acc = make_float4(0.f, 0.f, 0.f, 0.f);
        for (int n = warp; n < N; n += 8) {
            float4 v = *(const float4*)(embB + (size_t)n * E + lane * 4);
            acc.x += v.x; acc.y += v.y; acc.z += v.z; acc.w += v.w;
        }
        float4* red4 = (float4*)(sm + SM_COMPAT);
        red4[warp * 32 + lane] = acc;
        __syncthreads();
        if (warp == 0) {
            float4 s = red4[lane];
            #pragma unroll
            for (int r = 1; r < 8; r++) {
                float4 v = red4[r * 32 + lane];
                s.x += v.x; s.y += v.y; s.z += v.z; s.w += v.w;
            }
            float invN = 1.0f / (float)N;
            sm[SM_CTX + lane * 4 + 0] = s.x * invN;
            sm[SM_CTX + lane * 4 + 1] = s.y * invN;
            sm[SM_CTX + lane * 4 + 2] = s.z * invN;
            sm[SM_CTX + lane * 4 + 3] = s.w * invN;
        } else if (warp == 1) {
            int cn = cur[b];
            float4 v = *(const float4*)(embB + (size_t)cn * E + lane * 4);
            sm[SM_CTX + 128 + lane * 4 + 0] = v.x;
            sm[SM_CTX + 128 + lane * 4 + 1] = v.y;
            sm[SM_CTX + 128 + lane * 4 + 2] = v.z;
            sm[SM_CTX + 128 + lane * 4 + 3] = v.w;
        }
        if (t == 255) sm[SM_CTX + 256] = rc[b];
        __syncthreads();
    }

    // ---------------- Phase 1: q = context @ Wqg ---------------------------
    if (t < 128) {
        float acc = 0.f;
        #pragma unroll 1
        for (int c = 0; c < CTXLEN; c++)
            acc = fmaf(sm[SM_CTX + c], Wqg[c * E + t], acc);
        sm[SM_VA + t] = acc;   // q[128] = [H][D]
    }
    __syncthreads();

    // ---------------- Phase 2: qk[h][f] = sum_d Wkg[f][h*16+d]*q[h*16+d] ---
    // stage Wkg into s_tile at stride 129 (coalesced load, conflict-free read)
    for (int idx = t; idx < E * E; idx += THREADS)
        sm[SM_TILE + (idx >> 7) * 129 + (idx & 127)] = Wkg[idx];
    __syncthreads();
    #pragma unroll
    for (int k = 0; k < 4; k++) {
        int o = k * 256 + t;
        int h = o >> 7, f = o & 127;
        float acc = 0.f;
        #pragma unroll
        for (int d = 0; d < 16; d++)
            acc = fmaf(sm[SM_VA + h * 16 + d], sm[SM_TILE + f * 129 + h * 16 + d], acc);
        sm[SM_QK + h * 132 + f] = acc;
    }
    __syncthreads();

    // ---------------- Phase 3: flash attention over nodes ------------------
    // warp == head. wemb held in registers: lane owns floats [4*lane, 4*lane+4)
    float m_run = -1e30f, l_run = 0.f;
    float wx = 0.f, wy = 0.f, wz = 0.f, ww = 0.f;

    for (int n0 = 0; n0 < N; n0 += TN) {
        const int cnt = min(TN, N - n0);
        // load tile [cnt][128] -> s_tile stride 132
        for (int j = t; j < cnt * 32; j += THREADS) {
            int i = j >> 5, c4 = j & 31;
            float4 v = *(const float4*)(embB + (size_t)(n0 + i) * E + c4 * 4);
            *(float4*)(sm + SM_TILE + i * 132 + c4 * 4) = v;
        }
        __syncthreads();

        // compat: 1024 (h,i) pairs, 4 per thread (same h, 4 i's)
        #pragma unroll
        for (int k = 0; k < 4; k++) {
            int p = k * 256 + t;
            int i = p >> 3, h = p & 7;
            float c = -1e30f;
            if (i < cnt) {
                float acc = 0.f;
                const float4* qk4 = (const float4*)(sm + SM_QK + h * 132);
                const float4* e4p = (const float4*)(sm + SM_TILE + i * 132);
                #pragma unroll 8
                for (int f4 = 0; f4 < 32; f4++) {
                    float4 q4 = qk4[f4];
                    float4 e4 = e4p[f4];
                    acc = fmaf(q4.x, e4.x, acc);
                    acc = fmaf(q4.y, e4.y, acc);
                    acc = fmaf(q4.z, e4.z, acc);
                    acc = fmaf(q4.w, e4.w, acc);
                }
                if (!maskB[n0 + i]) c = acc * 0.25f;  // 1/sqrt(D)
            }
            sm[SM_COMPAT + h * TN + i] = c;
        }
        __syncthreads();

        // per-head online softmax update (warp h)
        {
            const int h = warp;
            float c0 = sm[SM_COMPAT + h * TN + lane];
            float c1 = sm[SM_COMPAT + h * TN + lane + 32];
            float c2 = sm[SM_COMPAT + h * TN + lane + 64];
            float c3 = sm[SM_COMPAT + h * TN + lane + 96];
            float tm = warp_max(fmaxf(fmaxf(c0, c1), fmaxf(c2, c3)));
            float m_new = fmaxf(m_run, tm);
            float alpha = __expf(m_run - m_new);
            float p0 = __expf(c0 - m_new);
            float p1 = __expf(c1 - m_new);
            float p2 = __expf(c2 - m_new);
            float p3 = __expf(c3 - m_new);
            sm[SM_P + h * TN + lane]      = p0;
            sm[SM_P + h * TN + lane + 32] = p1;
            sm[SM_P + h * TN + lane + 64] = p2;
            sm[SM_P + h * TN + lane + 96] = p3;
            float ps = warp_sum(p0 + p1 + p2 + p3);
            l_run = l_run * alpha + ps;
            m_run = m_new;
            wx *= alpha; wy *= alpha; wz *= alpha; ww *= alpha;
            __syncwarp();
            #pragma unroll 4
            for (int i = 0; i < cnt; i++) {
                float pv = sm[SM_P + h * TN + i];
                float4 e4 = *(const float4*)(sm + SM_TILE + i * 132 + lane * 4);
                wx = fmaf(pv, e4.x, wx);
                wy = fmaf(pv, e4.y, wy);
                wz = fmaf(pv, e4.z, wz);
                ww = fmaf(pv, e4.w, ww);
            }
        }
        __syncthreads();
    }

    // normalize wemb and park in smem
    {
        const int h = warp;
        float inv_l = 1.0f / l_run;
        sm[SM_WEMB + h * 128 + lane * 4 + 0] = wx * inv_l;
        sm[SM_WEMB + h * 128 + lane * 4 + 1] = wy * inv_l;
        sm[SM_WEMB + h * 128 + lane * 4 + 2] = wz * inv_l;
        sm[SM_WEMB + h * 128 + lane * 4 + 3] = ww * inv_l;
    }
    __syncthreads();

    // ---------------- Phase 4: heads -> glimpse -> qo -> qk2 ---------------
    if (t < 128) {        // heads[j] = sum_f wemb[h][f] * Wvg[f][j]
        int h = t >> 4;
        float acc = 0.f;
        #pragma unroll 4
        for (int f = 0; f < 128; f++)
            acc = fmaf(sm[SM_WEMB + h * 128 + f], Wvg[f * E + t], acc);
        sm[SM_VB + t] = acc;
    }
    __syncthreads();
    if (t < 128) {        // glimpse[e] = sum_e2 heads[e2]*Wog[e2][e]
        float acc = 0.f;
        #pragma unroll 4
        for (int e2 = 0; e2 < 128; e2++)
            acc = fmaf(sm[SM_VB + e2], Wog[e2 * E + t], acc);
        sm[SM_VA + t] = acc;
    }
    __syncthreads();
    if (t < 128) {        // qo[e] = sum_e2 glimpse[e2]*Wqo[e2][e]
        float acc = 0.f;
        #pragma unroll 4
        for (int e2 = 0; e2 < 128; e2++)
            acc = fmaf(sm[SM_VA + e2], Wqo[e2 * E + t], acc);
        sm[SM_VB + t] = acc;
    }
    __syncthreads();
    // stage Wko (row-major [f][e]) into s_tile at stride 129
    for (int idx = t; idx < E * E; idx += THREADS)
        sm[SM_TILE + (idx >> 7) * 129 + (idx & 127)] = Wko[idx];
    __syncthreads();
    if (t < 128) {        // qk2[f] = sum_e Wko[f][e]*qo[e]
        float acc = 0.f;
        #pragma unroll 4
        for (int e2 = 0; e2 < 128; e2++)
            acc = fmaf(sm[SM_TILE + t * 129 + e2], sm[SM_VB + e2], acc);
        sm[SM_QK2 + t] = acc;
    }
    __syncthreads();

    // ---------------- Phase 5: logits pass (warp per node) -----------------
    {
        float4 q4 = *(const float4*)(sm + SM_QK2 + lane * 4);
        const float inv_sqrtE = 0.08838834764831845f;  // 1/sqrt(128)
        for (int n = warp; n < N; n += 8) {
            float4 e4 = *(const float4*)(embB + (size_t)n * E + lane * 4);
            float d = e4.x * q4.x + e4.y * q4.y + e4.z * q4.z + e4.w * q4.w;
            d = warp_sum(d);
            if (lane == 0) {
                float lg = TANH_CLIP * tanhf(d * inv_sqrtE);
                if (maskB[n]) lg = -INFINITY;
                sm[SM_LOGITS + n] = lg;
            }
        }
    }
    __syncthreads();

    // ---------------- Phase 6: block softmax over logits -------------------
    float mx = -INFINITY;
    for (int n = t; n < N; n += THREADS) mx = fmaxf(mx, sm[SM_LOGITS + n]);
    mx = warp_max(mx);
    if (lane == 0) sm[SM_RED + warp] = mx;
    __syncthreads();
    if (t == 0) {
        float v = sm[SM_RED + 0];
        #pragma unroll
        for (int r = 1; r < 8; r++) v = fmaxf(v, sm[SM_RED + r]);
        sm[SM_RED + 8] = v;
    }
    __syncthreads();
    mx = sm[SM_RED + 8];

    float se = 0.f;
    for (int n = t; n < N; n += THREADS) se += __expf(sm[SM_LOGITS + n] - mx);
    se = warp_sum(se);
    if (lane == 0) sm[SM_RED + 16 + warp] = se;
    __syncthreads();
    if (t == 0) {
        float v = 0.f;
        #pragma unroll
        for (int r = 0; r < 8; r++) v += sm[SM_RED + 16 + r];
        sm[SM_RED + 24] = v;
    }
    __syncthreads();
    float inv_se = 1.0f / sm[SM_RED + 24];

    const size_t BN = (size_t)B * N;
    for (int n = t; n < N; n += THREADS) {
        float lg = sm[SM_LOGITS + n];
        out[(size_t)b * N + n]      = __expf(lg - mx) * inv_se;  // probs
        out[BN + (size_t)b * N + n] = lg;                        // logits
    }
}

extern "C" void kernel_launch(void* const* d_in, const int* in_sizes, int n_in,
                              void* d_out, int out_size) {
    const float* emb = (const float*)d_in[0];
    const float* rc  = (const float*)d_in[1];
    const float* Wqg = (const float*)d_in[2];
    const float* Wkg = (const float*)d_in[3];
    const float* Wvg = (const float*)d_in[4];
    const float* Wog = (const float*)d_in[5];
    const float* Wqo = (const float*)d_in[6];
    const float* Wko = (const float*)d_in[7];
    const int*   cur = (const int*)d_in[8];
    const unsigned char* mask = (const unsigned char*)d_in[9];

    int B = in_sizes[1];                 // remaining_capacity is [B]
    int N = in_sizes[0] / (B * E);       // embeddings is [B,N,E]
    float* out = (float*)d_out;

    size_t smem = SM_FLOATS * sizeof(float);
    cudaFuncSetAttribute(decoder_fused_kernel,
                         cudaFuncAttributeMaxDynamicSharedMemorySize, (int)smem);
    decoder_fused_kernel<<<B, THREADS, smem>>>(
        emb, rc, Wqg, Wkg, Wvg, Wog, Wqo, Wko, cur, mask, out, N, B);
}

// round 3
// speedup vs baseline: 1.9013x; 1.9013x over previous
#include <cuda_runtime.h>
#include <math.h>

#define E 128
#define H 8
#define CTXLEN 257
#define THREADS 256
#define TANH_CLIP 10.0f

#define MAXB 1024
#define MAXNC 16          // chunks of 64 nodes, supports N <= 1024
#define CHUNK 64
#define LCHUNK 128        // logits chunk

// ---------------- device scratch (static, no runtime alloc) ----------------
__device__ float g_mean[MAXB * E];               // 512 KB
__device__ float g_qk[MAXB * H * E];             // 4 MB
__device__ float g_qk2[MAXB * E];                // 512 KB
__device__ float g_pm[MAXB * MAXNC * H];         // per-chunk per-head max
__device__ float g_pl[MAXB * MAXNC * H];         // per-chunk per-head sumexp
__device__ float g_pw[MAXB * MAXNC * H * E];     // 64 MB unnormalized wemb
__device__ float g_sumexp[MAXB];

__device__ __forceinline__ float warp_max(float v) {
    #pragma unroll
    for (int o = 16; o; o >>= 1) v = fmaxf(v, __shfl_xor_sync(0xffffffffu, v, o));
    return v;
}
__device__ __forceinline__ float warp_sum(float v) {
    #pragma unroll
    for (int o = 16; o; o >>= 1) v += __shfl_xor_sync(0xffffffffu, v, o);
    return v;
}

// ---------------- K1: graph mean ----------------
__global__ __launch_bounds__(THREADS) void k_mean(const float* __restrict__ emb, int N) {
    const int b = blockIdx.x, t = threadIdx.x, lane = t & 31, warp = t >> 5;
    __shared__ float4 red[THREADS];
    const float* embB = emb + (size_t)b * N * E;
    float4 acc = make_float4(0.f, 0.f, 0.f, 0.f);
    #pragma unroll 4
    for (int n = warp; n < N; n += 8) {
        float4 v = *(const float4*)(embB + (size_t)n * E + lane * 4);
        acc.x += v.x; acc.y += v.y; acc.z += v.z; acc.w += v.w;
    }
    red[t] = acc;
    __syncthreads();
    if (warp == 0) {
        float4 s = red[lane];
        #pragma unroll
        for (int r = 1; r < 8; r++) {
            float4 v = red[r * 32 + lane];
            s.x += v.x; s.y += v.y; s.z += v.z; s.w += v.w;
        }
        float invN = 1.0f / (float)N;
        float* mb = g_mean + b * E + lane * 4;
        mb[0] = s.x * invN; mb[1] = s.y * invN; mb[2] = s.z * invN; mb[3] = s.w * invN;
    }
}

// ---------------- K2: context -> q -> qk (Wkg folded into query) ----------------
// dyn smem: WKG[128*129]=16512 | CTX[260] | Q[128]  -> 16900 floats
#define K2_WKG 0
#define K2_CTX 16512
#define K2_Q   (16512 + 260)
#define K2_FLOATS (K2_Q + 128)
__global__ __launch_bounds__(THREADS) void k_ctx(
    const float* __restrict__ emb, const float* __restrict__ rc,
    const float* __restrict__ Wqg, const float* __restrict__ Wkg,
    const int* __restrict__ cur, int N)
{
    extern __shared__ float sm[];
    const int b = blockIdx.x, t = threadIdx.x;

    for (int idx = t; idx < E * E; idx += THREADS)
        sm[K2_WKG + (idx >> 7) * 129 + (idx & 127)] = Wkg[idx];
    if (t < 128) sm[K2_CTX + t] = g_mean[b * E + t];
    else         sm[K2_CTX + t] = emb[(size_t)b * N * E + (size_t)cur[b] * E + (t - 128)];
    if (t == 0) { sm[K2_CTX + 256] = rc[b]; g_sumexp[b] = 0.f; }
    __syncthreads();

    if (t < 128) {
        float acc = 0.f;
        #pragma unroll 4
        for (int c = 0; c < CTXLEN; c++)
            acc = fmaf(sm[K2_CTX + c], Wqg[c * E + t], acc);
        sm[K2_Q + t] = acc;
    }
    __syncthreads();

    #pragma unroll
    for (int k = 0; k < 4; k++) {
        int o = k * THREADS + t;
        int h = o >> 7, f = o & 127;
        float acc = 0.f;
        #pragma unroll
        for (int d = 0; d < 16; d++)
            acc = fmaf(sm[K2_Q + h * 16 + d], sm[K2_WKG + f * 129 + h * 16 + d], acc);
        g_qk[b * (H * E) + h * E + f] = acc;
    }
}

// ---------------- K3: split-K flash partials ----------------
__global__ __launch_bounds__(THREADS) void k_flash(
    const float* __restrict__ emb, const unsigned char* __restrict__ mask, int N)
{
    __shared__ float s_tile[CHUNK * 132];
    __shared__ float s_qk[H * 132];
    __shared__ float s_c[H * CHUNK];
    __shared__ float s_p[H * CHUNK];

    const int c = blockIdx.x, b = blockIdx.y;
    const int t = threadIdx.x, lane = t & 31, warp = t >> 5;
    const int n0 = c * CHUNK;
    const int cnt = min(CHUNK, N - n0);

    for (int idx = t; idx < H * E; idx += THREADS)
        s_qk[(idx >> 7) * 132 + (idx & 127)] = g_qk[b * (H * E) + idx];

    const float* embB = emb + ((size_t)b * N + n0) * E;
    for (int j = t; j < cnt * 32; j += THREADS) {
        int i = j >> 5, c4 = j & 31;
        *(float4*)(s_tile + i * 132 + c4 * 4) =
            *(const float4*)(embB + (size_t)i * E + c4 * 4);
    }
    __syncthreads();

    // compat: 512 (h,i) pairs, 2 per thread
    #pragma unroll
    for (int k = 0; k < 2; k++) {
        int p = k * THREADS + t;
        int i = p >> 3, h = p & 7;
        float cc = -1e30f;
        if (i < cnt && !mask[(size_t)b * N + n0 + i]) {
            float acc = 0.f;
            const float4* qk4 = (const float4*)(s_qk + h * 132);
            const float4* e4p = (const float4*)(s_tile + i * 132);
            #pragma unroll 8
            for (int f4 = 0; f4 < 32; f4++) {
                float4 q4 = qk4[f4];
                float4 e4 = e4p[f4];
                acc = fmaf(q4.x, e4.x, acc);
                acc = fmaf(q4.y, e4.y, acc);
                acc = fmaf(q4.z, e4.z, acc);
                acc = fmaf(q4.w, e4.w, acc);
            }
            cc = acc * 0.25f;  // 1/sqrt(D=16)
        }
        s_c[h * CHUNK + i] = cc;
    }
    __syncthreads();

    // per-head local softmax partial (warp == head)
    {
        const int h = warp;
        float c0 = s_c[h * CHUNK + lane];
        float c1 = s_c[h * CHUNK + lane + 32];
        float m = warp_max(fmaxf(c0, c1));
        float p0 = __expf(c0 - m);
        float p1 = __expf(c1 - m);
        if (lane >= cnt)      p0 = 0.f;
        if (lane + 32 >= cnt) p1 = 0.f;
        s_p[h * CHUNK + lane]      = p0;
        s_p[h * CHUNK + lane + 32] = p1;
        float l = warp_sum(p0 + p1);
        __syncwarp();

        float wx = 0.f, wy = 0.f, wz = 0.f, ww = 0.f;
        #pragma unroll 4
        for (int i = 0; i < cnt; i++) {
            float pv = s_p[h * CHUNK + i];
            float4 e4 = *(const float4*)(s_tile + i * 132 + lane * 4);
            wx = fmaf(pv, e4.x, wx);
            wy = fmaf(pv, e4.y, wy);
            wz = fmaf(pv, e4.z, wz);
            ww = fmaf(pv, e4.w, ww);
        }
        const int base = (b * MAXNC + c) * H + h;
        if (lane == 0) { g_pm[base] = m; g_pl[base] = l; }
        *(float4*)(g_pw + (size_t)base * E + lane * 4) = make_float4(wx, wy, wz, ww);
    }
}

// ---------------- K4: combine partials + matvec chain -> qk2 ----------------
// dyn smem: WKO[128*129]=16512 | WEMB[1024] | VA[128] | VB[128] -> 17792 floats
#define K4_WKO  0
#define K4_WEMB 16512
#define K4_VA   (K4_WEMB + 1024)
#define K4_VB   (K4_VA + 128)
#define K4_FLOATS (K4_VB + 128)
__global__ __launch_bounds__(THREADS) void k_comb(
    const float* __restrict__ Wvg, const float* __restrict__ Wog,
    const float* __restrict__ Wqo, const float* __restrict__ Wko, int nchunk)
{
    extern __shared__ float sm[];
    const int b = blockIdx.x, t = threadIdx.x, lane = t & 31, warp = t >> 5;

    for (int idx = t; idx < E * E; idx += THREADS)
        sm[K4_WKO + (idx >> 7) * 129 + (idx & 127)] = Wko[idx];

    // combine per head (warp == head)
    {
        const int h = warp;
        float m = -1e30f;
        for (int c = 0; c < nchunk; c++)
            m = fmaxf(m, g_pm[(b * MAXNC + c) * H + h]);
        float L = 0.f;
        float4 w = make_float4(0.f, 0.f, 0.f, 0.f);
        for (int c = 0; c < nchunk; c++) {
            const int base = (b * MAXNC + c) * H + h;
            float s = __expf(g_pm[base] - m);
            L = fmaf(s, g_pl[base], L);
            float4 pw = *(const float4*)(g_pw + (size_t)base * E + lane * 4);
            w.x = fmaf(s, pw.x, w.x); w.y = fmaf(s, pw.y, w.y);
            w.z = fmaf(s, pw.z, w.z); w.w = fmaf(s, pw.w, w.w);
        }
        float invL = 1.0f / L;
        float* d = sm + K4_WEMB + h * E + lane * 4;
        d[0] = w.x * invL; d[1] = w.y * invL; d[2] = w.z * invL; d[3] = w.w * invL;
    }
    __syncthreads();

    if (t < 128) {           // heads[j] = sum_f wemb[h][f] * Wvg[f][j]
        int h = t >> 4;
        float acc = 0.f;
        #pragma unroll 4
        for (int f = 0; f < E; f++)
            acc = fmaf(sm[K4_WEMB + h * E + f], Wvg[f * E + t], acc);
        sm[K4_VA + t] = acc;
    }
    __syncthreads();
    if (t < 128) {           // glimpse
        float acc = 0.f;
        #pragma unroll 4
        for (int e2 = 0; e2 < E; e2++)
            acc = fmaf(sm[K4_VA + e2], Wog[e2 * E + t], acc);
        sm[K4_VB + t] = acc;
    }
    __syncthreads();
    if (t < 128) {           // qo
        float acc = 0.f;
        #pragma unroll 4
        for (int e2 = 0; e2 < E; e2++)
            acc = fmaf(sm[K4_VB + e2], Wqo[e2 * E + t], acc);
        sm[K4_VA + t] = acc;
    }
    __syncthreads();
    if (t < 128) {           // qk2[f] = sum_e Wko[f][e] * qo[e]
        float acc = 0.f;
        #pragma unroll 4
        for (int e2 = 0; e2 < E; e2++)
            acc = fmaf(sm[K4_WKO + t * 129 + e2], sm[K4_VA + e2], acc);
        g_qk2[b * E + t] = acc;
    }
}

// ---------------- K5: logits + sumexp (fixed shift = TANH_CLIP) ----------------
__global__ __launch_bounds__(THREADS) void k_logits(
    const float* __restrict__ emb, const unsigned char* __restrict__ mask,
    float* __restrict__ out, int N, int B)
{
    const int c = blockIdx.x, b = blockIdx.y;
    const int t = threadIdx.x, lane = t & 31, warp = t >> 5;
    const int n0 = c * LCHUNK;
    const int cnt = min(LCHUNK, N - n0);
    __shared__ float s_sum[8];

    float4 q4 = *(const float4*)(g_qk2 + b * E + lane * 4);
    const float inv_sqrtE = 0.08838834764831845f;  // 1/sqrt(128)
    const size_t BN = (size_t)B * N;
    const float* embB = emb + ((size_t)b * N + n0) * E;

    float lsum = 0.f;
    for (int i = warp; i < cnt; i += 8) {
        float4 e4 = *(const float4*)(embB + (size_t)i * E + lane * 4);
        float d = e4.x * q4.x + e4.y * q4.y + e4.z * q4.z + e4.w * q4.w;
        d = warp_sum(d);
        float x = d * inv_sqrtE;
        x = fminf(fmaxf(x, -15.f), 15.f);
        float ex = __expf(2.f * x);
        float lg = TANH_CLIP * (ex - 1.f) / (ex + 1.f);
        if (mask[(size_t)b * N + n0 + i]) lg = -INFINITY;
        if (lane == 0) {
            out[BN + (size_t)b * N + n0 + i] = lg;
            lsum += __expf(lg - TANH_CLIP);
        }
    }
    if (lane == 0) s_sum[warp] = lsum;
    __syncthreads();
    if (t == 0) {
        float s = 0.f;
        #pragma unroll
        for (int w = 0; w < 8; w++) s += s_sum[w];
        atomicAdd(&g_sumexp[b], s);
    }
}

// ---------------- K6: probs ----------------
__global__ __launch_bounds__(THREADS) void k_probs(float* __restrict__ out, int N, int B) {
    const int b = blockIdx.x, t = threadIdx.x;
    const size_t BN = (size_t)B * N;
    float inv = 1.0f / g_sumexp[b];
    for (int n = t; n < N; n += THREADS) {
        float lg = out[BN + (size_t)b * N + n];
        out[(size_t)b * N + n] = __expf(lg - TANH_CLIP) * inv;
    }
}

// ---------------- launch ----------------
extern "C" void kernel_launch(void* const* d_in, const int* in_sizes, int n_in,
                              void* d_out, int out_size) {
    const float* emb = (const float*)d_in[0];
    const float* rc  = (const float*)d_in[1];
    const float* Wqg = (const float*)d_in[2];
    const float* Wkg = (const float*)d_in[3];
    const float* Wvg = (const float*)d_in[4];
    const float* Wog = (const float*)d_in[5];
    const float* Wqo = (const float*)d_in[6];
    const float* Wko = (const float*)d_in[7];
    const int*   cur = (const int*)d_in[8];
    const unsigned char* mask = (const unsigned char*)d_in[9];

    int B = in_sizes[1];
    int N = in_sizes[0] / (B * E);
    float* out = (float*)d_out;

    int nchunk  = (N + CHUNK - 1) / CHUNK;
    int nlchunk = (N + LCHUNK - 1) / LCHUNK;

    static bool attr_done = false;
    if (!attr_done) {
        cudaFuncSetAttribute(k_ctx,  cudaFuncAttributeMaxDynamicSharedMemorySize,
                             K2_FLOATS * (int)sizeof(float));
        cudaFuncSetAttribute(k_comb, cudaFuncAttributeMaxDynamicSharedMemorySize,
                             K4_FLOATS * (int)sizeof(float));
        attr_done = true;
    }

    k_mean<<<B, THREADS>>>(emb, N);
    k_ctx<<<B, THREADS, K2_FLOATS * sizeof(float)>>>(emb, rc, Wqg, Wkg, cur, N);
    k_flash<<<dim3(nchunk, B), THREADS>>>(emb, mask, N);
    k_comb<<<B, THREADS, K4_FLOATS * sizeof(float)>>>(Wvg, Wog, Wqo, Wko, nchunk);
    k_logits<<<dim3(nlchunk, B), THREADS>>>(emb, mask, out, N, B);
    k_probs<<<B, THREADS>>>(out, N, B);
}